// round 5
// baseline (speedup 1.0000x reference)
#include <cuda_runtime.h>
#include <math.h>

#define D        512
#define BMAX     16
#define NCHUNK   16
#define NEG_INF  -1e30f

// ---------------- scratch (no allocation allowed) ----------------
__device__ float g_q[BMAX * D];                    // q = query @ W_align^T + b_align
__device__ float g_pm[BMAX * NCHUNK];              // per-chunk running max
__device__ float g_ps[BMAX * NCHUNK];              // per-chunk denom (rel. to g_pm)
__device__ float g_pctx[BMAX * NCHUNK * D];        // per-chunk partial context
__device__ float g_ctx[BMAX * D];                  // combined, normalized context

// ---------------- K1: q = query @ W_align^T + b_align ----------------
// grid = (64, B/4), block = 256 (8 warps).
// Warp = one output dim d for 4 batches: W row loaded once, 4 query rows,
// 20 independent float4 loads in flight, 4x FMA per W byte.
__global__ void __launch_bounds__(256) k1_qproj(
    const float* __restrict__ query,
    const float* __restrict__ W_align,
    const float* __restrict__ b_align)
{
    const int warp = threadIdx.x >> 5;
    const int lane = threadIdx.x & 31;
    const int d    = blockIdx.x * 8 + warp;
    const int b0   = blockIdx.y * 4;

    const float4* wrow = reinterpret_cast<const float4*>(W_align + (size_t)d * D);
    float4 w[4];
#pragma unroll
    for (int k = 0; k < 4; k++) w[k] = wrow[lane + 32 * k];

    float acc[4] = {0.f, 0.f, 0.f, 0.f};
#pragma unroll
    for (int j = 0; j < 4; j++) {
        const float4* xq = reinterpret_cast<const float4*>(query + (size_t)(b0 + j) * D);
#pragma unroll
        for (int k = 0; k < 4; k++) {
            float4 x = xq[lane + 32 * k];
            acc[j] = fmaf(w[k].x, x.x, acc[j]); acc[j] = fmaf(w[k].y, x.y, acc[j]);
            acc[j] = fmaf(w[k].z, x.z, acc[j]); acc[j] = fmaf(w[k].w, x.w, acc[j]);
        }
    }
#pragma unroll
    for (int o = 16; o > 0; o >>= 1) {
#pragma unroll
        for (int j = 0; j < 4; j++) acc[j] += __shfl_xor_sync(0xffffffffu, acc[j], o);
    }
    if (lane < 4) g_q[(size_t)(b0 + lane) * D + d] = acc[lane] + b_align[d];
}

// ---------------- K2: single-pass online-softmax over value ----------------
// grid = B*NCHUNK (256 blocks = one resident wave), block = 256 (8 warps).
// Block compacts the unmasked rows of its 512-row chunk into smem, then warps
// consume them in a statically balanced interleave, 4 rows per iteration.
__global__ void __launch_bounds__(256) k2_attn(
    const float* __restrict__ value,
    const int*   __restrict__ mask,
    int L)
{
    const int b    = blockIdx.x / NCHUNK;
    const int c    = blockIdx.x % NCHUNK;
    const int RC   = L / NCHUNK;           // rows per chunk (512)
    const int l0   = c * RC;
    const int tid  = threadIdx.x;
    const int warp = tid >> 5;
    const int lane = tid & 31;

    __shared__ int   s_idx[512];
    __shared__ int   s_pop[16], s_off[16], s_total;

    // ---- compact unmasked row indices (deterministic) ----
    const int* mrow = mask + (size_t)b * L + l0;
    unsigned a0 = __ballot_sync(0xffffffffu, mrow[tid]       == 0);
    unsigned a1 = __ballot_sync(0xffffffffu, mrow[tid + 256] == 0);
    if (lane == 0) { s_pop[warp] = __popc(a0); s_pop[warp + 8] = __popc(a1); }
    __syncthreads();
    if (tid == 0) {
        int acc = 0;
#pragma unroll
        for (int i = 0; i < 16; i++) { s_off[i] = acc; acc += s_pop[i]; }
        s_total = acc;
    }
    __syncthreads();
    if ((a0 >> lane) & 1)
        s_idx[s_off[warp]     + __popc(a0 & ((1u << lane) - 1))] = warp * 32 + lane;
    if ((a1 >> lane) & 1)
        s_idx[s_off[warp + 8] + __popc(a1 & ((1u << lane) - 1))] = 256 + warp * 32 + lane;
    __syncthreads();
    const int T = s_total;

    // ---- q into registers (float4-strided) ----
    const float4* q4 = reinterpret_cast<const float4*>(g_q + b * D);
    float4 q[4];
#pragma unroll
    for (int k = 0; k < 4; k++) q[k] = q4[lane + 32 * k];

    float m = NEG_INF, s = 0.f;
    float4 ctx[4];
#pragma unroll
    for (int k = 0; k < 4; k++) ctx[k] = make_float4(0.f, 0.f, 0.f, 0.f);

    const float* vbase = value + ((size_t)b * L + l0) * D;

    for (int t0 = warp * 4; t0 < T; t0 += 32) {
        const int n = min(4, T - t0);
        const int j0 = s_idx[t0];
        const int j1 = s_idx[t0 + (n > 1 ? 1 : 0)];
        const int j2 = s_idx[t0 + (n > 2 ? 2 : 0)];
        const int j3 = s_idx[t0 + (n > 3 ? 3 : 0)];

        const float4* p0 = reinterpret_cast<const float4*>(vbase + (size_t)j0 * D);
        const float4* p1 = reinterpret_cast<const float4*>(vbase + (size_t)j1 * D);
        const float4* p2 = reinterpret_cast<const float4*>(vbase + (size_t)j2 * D);
        const float4* p3 = reinterpret_cast<const float4*>(vbase + (size_t)j3 * D);

        float4 v0[4], v1[4], v2[4], v3[4];
#pragma unroll
        for (int k = 0; k < 4; k++) v0[k] = __ldcs(p0 + lane + 32 * k);
#pragma unroll
        for (int k = 0; k < 4; k++) v1[k] = __ldcs(p1 + lane + 32 * k);
#pragma unroll
        for (int k = 0; k < 4; k++) v2[k] = __ldcs(p2 + lane + 32 * k);
#pragma unroll
        for (int k = 0; k < 4; k++) v3[k] = __ldcs(p3 + lane + 32 * k);

        float s0 = 0.f, s1 = 0.f, s2 = 0.f, s3 = 0.f;
#pragma unroll
        for (int k = 0; k < 4; k++) {
            s0 = fmaf(v0[k].x, q[k].x, s0); s0 = fmaf(v0[k].y, q[k].y, s0);
            s0 = fmaf(v0[k].z, q[k].z, s0); s0 = fmaf(v0[k].w, q[k].w, s0);
            s1 = fmaf(v1[k].x, q[k].x, s1); s1 = fmaf(v1[k].y, q[k].y, s1);
            s1 = fmaf(v1[k].z, q[k].z, s1); s1 = fmaf(v1[k].w, q[k].w, s1);
            s2 = fmaf(v2[k].x, q[k].x, s2); s2 = fmaf(v2[k].y, q[k].y, s2);
            s2 = fmaf(v2[k].z, q[k].z, s2); s2 = fmaf(v2[k].w, q[k].w, s2);
            s3 = fmaf(v3[k].x, q[k].x, s3); s3 = fmaf(v3[k].y, q[k].y, s3);
            s3 = fmaf(v3[k].w, q[k].w, s3); s3 = fmaf(v3[k].z, q[k].z, s3);
        }
#pragma unroll
        for (int o = 16; o > 0; o >>= 1) {
            s0 += __shfl_xor_sync(0xffffffffu, s0, o);
            s1 += __shfl_xor_sync(0xffffffffu, s1, o);
            s2 += __shfl_xor_sync(0xffffffffu, s2, o);
            s3 += __shfl_xor_sync(0xffffffffu, s3, o);
        }
        if (n < 2) s1 = NEG_INF;
        if (n < 3) s2 = NEG_INF;
        if (n < 4) s3 = NEG_INF;

        const float m_new = fmaxf(fmaxf(m, fmaxf(s0, s1)), fmaxf(s2, s3));
        const float corr = __expf(m  - m_new);
        const float w0   = __expf(s0 - m_new);
        const float w1   = __expf(s1 - m_new);
        const float w2   = __expf(s2 - m_new);
        const float w3   = __expf(s3 - m_new);
        s = s * corr + w0 + w1 + w2 + w3;
#pragma unroll
        for (int k = 0; k < 4; k++) {
            ctx[k].x = ctx[k].x * corr + fmaf(w1, v1[k].x, w0 * v0[k].x)
                                       + fmaf(w3, v3[k].x, w2 * v2[k].x);
            ctx[k].y = ctx[k].y * corr + fmaf(w1, v1[k].y, w0 * v0[k].y)
                                       + fmaf(w3, v3[k].y, w2 * v2[k].y);
            ctx[k].z = ctx[k].z * corr + fmaf(w1, v1[k].z, w0 * v0[k].z)
                                       + fmaf(w3, v3[k].z, w2 * v2[k].z);
            ctx[k].w = ctx[k].w * corr + fmaf(w1, v1[k].w, w0 * v0[k].w)
                                       + fmaf(w3, v3[k].w, w2 * v2[k].w);
        }
        m = m_new;
    }

    // ---- merge the 8 warps' partials ----
    __shared__ float sm_m[8], sm_s[8];
    __shared__ float sm_ctx[8][D];
    if (lane == 0) { sm_m[warp] = m; sm_s[warp] = s; }
#pragma unroll
    for (int k = 0; k < 4; k++) {
        const int i = (lane + 32 * k) * 4;
        sm_ctx[warp][i + 0] = ctx[k].x;
        sm_ctx[warp][i + 1] = ctx[k].y;
        sm_ctx[warp][i + 2] = ctx[k].z;
        sm_ctx[warp][i + 3] = ctx[k].w;
    }
    __syncthreads();

    float M = NEG_INF;
#pragma unroll
    for (int wi = 0; wi < 8; wi++) M = fmaxf(M, sm_m[wi]);

    float e[8];
#pragma unroll
    for (int wi = 0; wi < 8; wi++) e[wi] = __expf(sm_m[wi] - M);

    float o0 = 0.f, o1 = 0.f;
#pragma unroll
    for (int wi = 0; wi < 8; wi++) {
        o0 = fmaf(sm_ctx[wi][tid],       e[wi], o0);
        o1 = fmaf(sm_ctx[wi][tid + 256], e[wi], o1);
    }
    const int pidx = b * NCHUNK + c;
    g_pctx[(size_t)pidx * D + tid]       = o0;
    g_pctx[(size_t)pidx * D + tid + 256] = o1;

    if (tid == 0) {
        float S = 0.f;
#pragma unroll
        for (int wi = 0; wi < 8; wi++) S = fmaf(sm_s[wi], e[wi], S);
        g_pm[pidx] = M;
        g_ps[pidx] = S;
    }
}

// ---------------- K3a: combine chunk partials -> g_ctx (normalized) ----------------
// grid = (B, 2), block = 256. Each thread combines ONE d-column across 16
// chunks (MLP = 16 independent loads).
__global__ void __launch_bounds__(256) k3a_combine()
{
    const int b   = blockIdx.x;
    const int d   = blockIdx.y * 256 + threadIdx.x;
    const int tid = threadIdx.x;
    __shared__ float e_sm[NCHUNK];
    __shared__ float Sinv_sm;

    float M = NEG_INF;
#pragma unroll
    for (int c = 0; c < NCHUNK; c++) M = fmaxf(M, g_pm[b * NCHUNK + c]);
    if (tid < NCHUNK)
        e_sm[tid] = __expf(g_pm[b * NCHUNK + tid] - M);
    __syncthreads();

    if (tid == 0) {
        float S = 0.f;
#pragma unroll
        for (int c = 0; c < NCHUNK; c++) S = fmaf(g_ps[b * NCHUNK + c], e_sm[c], S);
        Sinv_sm = 1.f / S;
    }
    __syncthreads();
    const float Sinv = Sinv_sm;

    float acc = 0.f;
#pragma unroll
    for (int c = 0; c < NCHUNK; c++)
        acc = fmaf(g_pctx[((size_t)b * NCHUNK + c) * D + d], e_sm[c], acc);
    g_ctx[(size_t)b * D + d] = acc * Sinv;
}

// ---------------- K3b: out = tanh(ctx@Wv^T + bv + q@Wq^T + bq) ----------------
// grid = (64, B/4), block = 256 (8 warps).
// Warp = one output dim d for 4 batches: Wv+Wq rows loaded once (8 float4),
// then 4 independent (ctx,q) row pairs; 4 accumulators, one reduce.
__global__ void __launch_bounds__(256) k3b_out(
    const float* __restrict__ W_query,
    const float* __restrict__ b_query,
    const float* __restrict__ W_value,
    const float* __restrict__ b_value,
    float* __restrict__ out)
{
    const int warp = threadIdx.x >> 5;
    const int lane = threadIdx.x & 31;
    const int d    = blockIdx.x * 8 + warp;
    const int b0   = blockIdx.y * 4;

    const float4* wvp = reinterpret_cast<const float4*>(W_value + (size_t)d * D);
    const float4* wqp = reinterpret_cast<const float4*>(W_query + (size_t)d * D);
    float4 wv[4], wq[4];
#pragma unroll
    for (int k = 0; k < 4; k++) { wv[k] = wvp[lane + 32 * k]; wq[k] = wqp[lane + 32 * k]; }

    float acc[4] = {0.f, 0.f, 0.f, 0.f};
#pragma unroll
    for (int j = 0; j < 4; j++) {
        const float4* cxp = reinterpret_cast<const float4*>(g_ctx + (size_t)(b0 + j) * D);
        const float4* qxp = reinterpret_cast<const float4*>(g_q   + (size_t)(b0 + j) * D);
#pragma unroll
        for (int k = 0; k < 4; k++) {
            float4 cx = cxp[lane + 32 * k];
            float4 qx = qxp[lane + 32 * k];
            acc[j] = fmaf(wv[k].x, cx.x, acc[j]); acc[j] = fmaf(wv[k].y, cx.y, acc[j]);
            acc[j] = fmaf(wv[k].z, cx.z, acc[j]); acc[j] = fmaf(wv[k].w, cx.w, acc[j]);
            acc[j] = fmaf(wq[k].x, qx.x, acc[j]); acc[j] = fmaf(wq[k].y, qx.y, acc[j]);
            acc[j] = fmaf(wq[k].z, qx.z, acc[j]); acc[j] = fmaf(wq[k].w, qx.w, acc[j]);
        }
    }
#pragma unroll
    for (int o = 16; o > 0; o >>= 1) {
#pragma unroll
        for (int j = 0; j < 4; j++) acc[j] += __shfl_xor_sync(0xffffffffu, acc[j], o);
    }
    if (lane < 4)
        out[(size_t)(b0 + lane) * D + d] = tanhf(acc[lane] + b_value[d] + b_query[d]);
}

// ---------------- launch ----------------
extern "C" void kernel_launch(void* const* d_in, const int* in_sizes, int n_in,
                              void* d_out, int out_size)
{
    const float* query   = (const float*)d_in[0];
    const float* value   = (const float*)d_in[1];
    const int*   mask    = (const int*)  d_in[2];
    const float* W_align = (const float*)d_in[3];
    const float* b_align = (const float*)d_in[4];
    const float* W_query = (const float*)d_in[5];
    const float* b_query = (const float*)d_in[6];
    const float* W_value = (const float*)d_in[7];
    const float* b_value = (const float*)d_in[8];
    float* out = (float*)d_out;

    const int B = in_sizes[0] / D;          // 16
    const int L = in_sizes[2] / B;          // 8192

    k1_qproj   <<<dim3(64, B / 4), 256>>>(query, W_align, b_align);
    k2_attn    <<<B * NCHUNK, 256>>>(value, mask, L);
    k3a_combine<<<dim3(B, 2), 256>>>();
    k3b_out    <<<dim3(64, B / 4), 256>>>(W_query, b_query, W_value, b_value, out);
}